// round 12
// baseline (speedup 1.0000x reference)
#include <cuda_runtime.h>

#define DIM 128
#define MAX_NODES 50000
#define CAP 192                               // bucket capacity per node

typedef unsigned long long ull;

// Scratch (device globals — no allocation allowed)
__device__ float g_h[MAX_NODES * DIM];        // h = x @ W^T (raw, fp32)
__device__ int   g_cnt_row[MAX_NODES];        // in-degree by destination
__device__ int   g_cnt_col[MAX_NODES];        // degree by source (normalization)
__device__ int   g_bucket[MAX_NODES * CAP];   // per-node edge buckets (col ids)
__device__ int   g_is64;

// f32x2 packed math (SASS FFMA2 — only reachable via PTX)
#define FMA2(d, a, b, c) \
    asm("fma.rn.f32x2 %0, %1, %2, %3;" : "=l"(d) : "l"(a), "l"(b), "l"(c))
#define PACK2(d, lo, hi) \
    asm("mov.b64 %0, {%1, %2};" : "=l"(d) : "f"(lo), "f"(hi))
#define UNPACK2(lo, hi, v) \
    asm("mov.b64 {%0, %1}, %2;" : "=f"(lo), "=f"(hi) : "l"(v))

__device__ __forceinline__ int edge_at(const int* __restrict__ p, int idx) {
    return g_is64 ? p[2 * idx] : p[idx];
}

// ---------------------------------------------------------------------------
// Prep: zero counters; warp-parallel dtype detect (int64 LE => odd words all 0).
// ---------------------------------------------------------------------------
__global__ void k_prep(const int* __restrict__ p, int n_elems, int N) {
    int i = blockIdx.x * blockDim.x + threadIdx.x;
    if (i < N) { g_cnt_row[i] = 0; g_cnt_col[i] = 0; }
    if (blockIdx.x == 0 && threadIdx.x < 32) {
        int lim = n_elems < 4096 ? n_elems : 4096;
        int bad = 0;
        for (int w = threadIdx.x; 2 * w + 1 < lim; w += 32)
            if (p[2 * w + 1] != 0) bad = 1;
        unsigned m = __ballot_sync(0xFFFFFFFFu, bad);
        if (threadIdx.x == 0) g_is64 = (m == 0) ? 1 : 0;
    }
}

// ---------------------------------------------------------------------------
// Direct bucket fill, 2 edges per thread for MLP (both streams coalesced).
// Row slot via atomic bump; col degree counted in the same pass.
// ---------------------------------------------------------------------------
__global__ void k_fill(const int* __restrict__ p, int E) {
    int E2 = (E + 1) >> 1;
    int t = blockIdx.x * blockDim.x + threadIdx.x;
    if (t >= E2) return;
    int e1 = t + E2;
    bool has2 = (e1 < E);

    // Front-batch all loads
    int r0 = edge_at(p, t);
    int c0 = edge_at(p, E + t);
    int r1 = 0, c1 = 0;
    if (has2) {
        r1 = edge_at(p, e1);
        c1 = edge_at(p, E + e1);
    }

    int p0 = atomicAdd(&g_cnt_row[r0], 1);
    if (p0 < CAP) g_bucket[r0 * CAP + p0] = c0;
    atomicAdd(&g_cnt_col[c0], 1);
    if (has2) {
        int p1 = atomicAdd(&g_cnt_row[r1], 1);
        if (p1 < CAP) g_bucket[r1 * CAP + p1] = c1;
        atomicAdd(&g_cnt_col[c1], 1);
    }
}

// ---------------------------------------------------------------------------
// GEMM: h[m][c] = sum_k x[m][k] * W[c][k]  (fp32; independent of CSR)
// 64 rows/block, 256 threads, 8x4 register tile via packed f32x2 FMA.
// ---------------------------------------------------------------------------
#define TM 64
#define KC 32
#define WT_STRIDE 132
#define XT_STRIDE 68

__global__ __launch_bounds__(256) void k_gemm(const float* __restrict__ x,
                                              const float* __restrict__ W, int N) {
    __shared__ float Wt[KC * WT_STRIDE];  // Wt[kk][c]
    __shared__ float xt[KC * XT_STRIDE];  // xt[kk][m]

    int t = threadIdx.x;
    int m_base = blockIdx.x * TM;
    int c0 = (t & 31) * 4;
    int m0 = (t >> 5) * 8;

    ull a01[8], a23[8];
#pragma unroll
    for (int i = 0; i < 8; i++) { a01[i] = 0ull; a23[i] = 0ull; }

    for (int kb = 0; kb < DIM; kb += KC) {
        __syncthreads();
        for (int i = t; i < DIM * KC; i += 256) {
            int kk = i & (KC - 1);
            int c  = i >> 5;
            Wt[kk * WT_STRIDE + c] = W[c * DIM + kb + kk];
        }
        for (int i = t; i < TM * KC; i += 256) {
            int kk = i & (KC - 1);
            int m  = i >> 5;
            int gm = m_base + m;
            xt[kk * XT_STRIDE + m] = (gm < N) ? x[(size_t)gm * DIM + kb + kk] : 0.0f;
        }
        __syncthreads();

#pragma unroll 4
        for (int kk = 0; kk < KC; kk++) {
            float4 wv = *(const float4*)&Wt[kk * WT_STRIDE + c0];
            ull b01, b23;
            PACK2(b01, wv.x, wv.y);
            PACK2(b23, wv.z, wv.w);
            float4 xa = *(const float4*)&xt[kk * XT_STRIDE + m0];
            float4 xb = *(const float4*)&xt[kk * XT_STRIDE + m0 + 4];
            float xr[8] = {xa.x, xa.y, xa.z, xa.w, xb.x, xb.y, xb.z, xb.w};
#pragma unroll
            for (int i = 0; i < 8; i++) {
                ull av;
                PACK2(av, xr[i], xr[i]);
                FMA2(a01[i], av, b01, a01[i]);
                FMA2(a23[i], av, b23, a23[i]);
            }
        }
    }

#pragma unroll
    for (int i = 0; i < 8; i++) {
        int gm = m_base + m0 + i;
        if (gm < N) {
            float4 hv;
            UNPACK2(hv.x, hv.y, a01[i]);
            UNPACK2(hv.z, hv.w, a23[i]);
            *(float4*)&g_h[(size_t)gm * DIM + c0] = hv;
        }
    }
}

// ---------------------------------------------------------------------------
// Gather: one warp per destination node. Lane l owns floats [4l, 4l+4).
// dinv computed inline from cnt_col (no separate dinv pass).
// Unroll-4 with next-id prefetch; 512-thread blocks, min 3 CTAs/SM for
// occupancy (regs ~40).
// ---------------------------------------------------------------------------
__global__ __launch_bounds__(512, 3) void k_gather(float* __restrict__ out, int N) {
    int gtid = blockIdx.x * blockDim.x + threadIdx.x;
    int i = gtid >> 5;
    int lane = gtid & 31;
    if (i >= N) return;

    float di = rsqrtf(1.0f + (float)g_cnt_col[i]);
    float4 hv = ((const float4*)(g_h + (size_t)i * DIM))[lane];
    float s = di * di;
    float4 acc = make_float4(hv.x * s, hv.y * s, hv.z * s, hv.w * s);

    const int* __restrict__ bkt = g_bucket + (size_t)i * CAP;
    int cnt = g_cnt_row[i];
    if (cnt > CAP) cnt = CAP;

    int j = 0;
    if (cnt >= 4) {
        // prime: load first 4 ids
        int c0 = bkt[0], c1 = bkt[1], c2 = bkt[2], c3 = bkt[3];
        for (;;) {
            int nj = j + 4;
            // issue row loads + degree loads for current batch
            float4 n0 = ((const float4*)(g_h + (size_t)c0 * DIM))[lane];
            float4 n1 = ((const float4*)(g_h + (size_t)c1 * DIM))[lane];
            float4 n2 = ((const float4*)(g_h + (size_t)c2 * DIM))[lane];
            float4 n3 = ((const float4*)(g_h + (size_t)c3 * DIM))[lane];
            int d0 = g_cnt_col[c0], d1 = g_cnt_col[c1];
            int d2 = g_cnt_col[c2], d3 = g_cnt_col[c3];
            // prefetch next ids while current loads are in flight
            bool more = (nj + 4 <= cnt);
            if (more) {
                c0 = bkt[nj + 0]; c1 = bkt[nj + 1];
                c2 = bkt[nj + 2]; c3 = bkt[nj + 3];
            }
            float w0 = di * rsqrtf(1.0f + (float)d0);
            float w1 = di * rsqrtf(1.0f + (float)d1);
            float w2 = di * rsqrtf(1.0f + (float)d2);
            float w3 = di * rsqrtf(1.0f + (float)d3);
            acc.x += w0 * n0.x + w1 * n1.x + w2 * n2.x + w3 * n3.x;
            acc.y += w0 * n0.y + w1 * n1.y + w2 * n2.y + w3 * n3.y;
            acc.z += w0 * n0.z + w1 * n1.z + w2 * n2.z + w3 * n3.z;
            acc.w += w0 * n0.w + w1 * n1.w + w2 * n2.w + w3 * n3.w;
            j = nj;
            if (!more) break;
        }
    }
    for (; j < cnt; j++) {
        int c = bkt[j];
        float4 nv = ((const float4*)(g_h + (size_t)c * DIM))[lane];
        float ww = di * rsqrtf(1.0f + (float)g_cnt_col[c]);
        acc.x += ww * nv.x;
        acc.y += ww * nv.y;
        acc.z += ww * nv.z;
        acc.w += ww * nv.w;
    }

    acc.x = fmaxf(acc.x, 0.0f);
    acc.y = fmaxf(acc.y, 0.0f);
    acc.z = fmaxf(acc.z, 0.0f);
    acc.w = fmaxf(acc.w, 0.0f);
    ((float4*)(out + (size_t)i * DIM))[lane] = acc;
}

// ---------------------------------------------------------------------------
extern "C" void kernel_launch(void* const* d_in, const int* in_sizes, int n_in,
                              void* d_out, int out_size) {
    const float* x  = (const float*)d_in[0];
    const float* W  = (const float*)d_in[1];
    const int*   ei = (const int*)d_in[2];
    float* out      = (float*)d_out;

    int N = in_sizes[0] / DIM;
    int E = in_sizes[2] / 2;
    int E2 = (E + 1) >> 1;

    // Fork a side branch for the GEMM (independent of the bucket build).
    cudaStream_t s2;
    cudaStreamCreateWithFlags(&s2, cudaStreamNonBlocking);
    cudaEvent_t evFork, evJoin;
    cudaEventCreateWithFlags(&evFork, cudaEventDisableTiming);
    cudaEventCreateWithFlags(&evJoin, cudaEventDisableTiming);

    cudaEventRecord(evFork, 0);
    cudaStreamWaitEvent(s2, evFork, 0);
    k_gemm<<<(N + TM - 1) / TM, 256, 0, s2>>>(x, W, N);
    cudaEventRecord(evJoin, s2);

    // Bucket build chain on the main (capture) stream
    k_prep<<<(N + 255) / 256, 256>>>(ei, in_sizes[2], N);
    k_fill<<<(E2 + 255) / 256, 256>>>(ei, E);

    // Join, then gather
    cudaStreamWaitEvent(0, evJoin, 0);
    k_gather<<<(N * 32 + 511) / 512, 512>>>(out, N);
}